// round 16
// baseline (speedup 1.0000x reference)
#include <cuda_runtime.h>
#include <math.h>
#include <stdint.h>

#define EPS 1e-5f
typedef unsigned long long ull;

// ---------------- persistent scratch ----------------
__device__ float g_layout[64 * 5 * 108 * 108];
__device__ float g_y1[64 * 32 * 52 * 52];        // conv1 raw out
__device__ float g_y1n[64 * 32 * 52 * 52];       // BN1+leaky applied, col51 zeroed
__device__ float g_w1t[125 * 32];                // conv1 weights [k=125][oc=32]
__device__ float g_w2t[32 * 25 * 64];            // conv2 weights [ic][kk][oc]
__device__ float g_y2[64 * 64 * 24 * 24];
__device__ float g_fc1[64 * 512];
__device__ double g_sum1[32], g_sq1[32];
__device__ double g_sum2[64], g_sq2[64];

// ---------------- f32x2 helpers ----------------
__device__ __forceinline__ ull fma2(ull a, ull b, ull c) {
    ull d;
    asm("fma.rn.f32x2 %0, %1, %2, %3;" : "=l"(d) : "l"(a), "l"(b), "l"(c));
    return d;
}
__device__ __forceinline__ ull pk2(float a, float b) {
    ull r;
    asm("mov.b64 %0, {%1, %2};" : "=l"(r) : "f"(a), "f"(b));
    return r;
}
__device__ __forceinline__ void upk2(ull v, float& a, float& b) {
    asm("mov.b64 {%0, %1}, %2;" : "=f"(a), "=f"(b) : "l"(v));
}
__device__ __forceinline__ float leaky(float v) { return v > 0.f ? v : 0.2f * v; }

// ---------------- K0: layout render (+ zeros + weight transposes) --------------
__global__ void layout_kernel(const float* __restrict__ img,
                              const float* __restrict__ w2,
                              const float* __restrict__ w1) {
    int b = blockIdx.y, t = threadIdx.x;
    int bid = b * 46 + blockIdx.x;
    if (bid < 128) g_fc1[bid * 256 + t] = 0.f;
    if (bid == 0) {
        if (t < 32) { g_sum1[t] = 0.0; g_sq1[t] = 0.0; }
        else if (t < 96) { g_sum2[t - 32] = 0.0; g_sq2[t - 32] = 0.0; }
    }
    if (bid < 200) {   // transpose conv2 weights: w2t[(ic*25+kk)*64+oc]
        int idx = bid * 256 + t;           // < 51200
        int oc = idx & 63, r = idx >> 6;
        int ic = r / 25, kk = r - 25 * ic;
        g_w2t[idx] = w2[(oc * 32 + ic) * 25 + kk];
    } else if (bid < 216) {  // transpose conv1 weights: w1t[k*32+oc]
        int idx = (bid - 200) * 256 + t;   // < 4096
        if (idx < 4000) {
            int oc = idx & 31, k = idx >> 5;
            g_w1t[idx] = w1[oc * 125 + k];
        }
    }
    __shared__ float so[81];
    if (t < 81) so[t] = img[b * 81 + t];
    __syncthreads();
    int p = blockIdx.x * 256 + t;
    if (p >= 11664) return;
    int y = p / 108, x = p - y * 108;
    float fx = (float)x, fy = (float)y;
    float m[5];
#pragma unroll
    for (int c = 0; c < 5; c++) m[c] = -3.4e38f;
#pragma unroll
    for (int o = 0; o < 9; o++) {
        const float* f = &so[o * 9];
        float xc = f[0] * 108.f, yc = f[1] * 108.f;
        float hw = f[2] * 54.f, hh = f[3] * 54.f;
        float x1 = xc - hw, x2 = xc + hw, y1 = yc - hh, y2 = yc + hh;
        float x1d = fx - x1, x2d = x2 - fx, y1d = fy - y1, y2d = y2 - fy;
        float yin = __saturatef(y1d) * __saturatef(y2d);
        float xin = __saturatef(x1d) * __saturatef(x2d);
        float l1 = fmaxf(1.f - fabsf(x1d), 0.f) * yin;
        float l2 = fmaxf(1.f - fabsf(x2d), 0.f) * yin;
        float l3 = fmaxf(1.f - fabsf(y1d), 0.f) * xin;
        float l4 = fmaxf(1.f - fabsf(y2d), 0.f) * xin;
        float xym = fmaxf(fmaxf(l1, l2), fmaxf(l3, l4));
#pragma unroll
        for (int c = 0; c < 5; c++) m[c] = fmaxf(m[c], xym * f[4 + c]);
    }
#pragma unroll
    for (int c = 0; c < 5; c++) g_layout[(b * 5 + c) * 11664 + p] = m[c];
}

// ---------------- K1: conv1 + fused BN1 raw stats (cp.async loads) -------------
// grid (13, 64), block 128 (104 active). Thread: 4 consecutive px * 16 oc (oh half).
__global__ __launch_bounds__(128, 4) void conv1_kernel() {
    __shared__ __align__(16) float sW[4000];        // [k=125][oc=32]
    __shared__ __align__(16) float sIn[5940];       // 5 ch x 11 rows x 108
    __shared__ float sRed[4 * 64];
    int b = blockIdx.y, tile = blockIdx.x, t = threadIdx.x;
    int r0 = 8 * tile;
    uint32_t sIn_b, sW_b;
    asm("{ .reg .u64 tmp; cvta.to.shared.u64 tmp, %1; cvt.u32.u64 %0, tmp; }"
        : "=r"(sIn_b) : "l"(sIn));
    asm("{ .reg .u64 tmp; cvta.to.shared.u64 tmp, %1; cvt.u32.u64 %0, tmp; }"
        : "=r"(sW_b) : "l"(sW));
#pragma unroll
    for (int k = 0; k < 20; k++) {
        int j = t + k * 128;
        if (j < 1485) {
            int ic = j / 297, off = j - ic * 297;
            const float* g = g_layout + (size_t)(b * 5 + ic) * 11664
                             + r0 * 108 + off * 4;
            uint32_t d = sIn_b + (ic * 1188 + off * 4) * 4;
            asm volatile("cp.async.cg.shared.global [%0], [%1], 16;"
                         :: "r"(d), "l"(g) : "memory");
        } else if (j < 2485) {
            int wj = j - 1485;
            const float* g = g_w1t + wj * 4;
            uint32_t d = sW_b + wj * 16;
            asm volatile("cp.async.cg.shared.global [%0], [%1], 16;"
                         :: "r"(d), "l"(g) : "memory");
        }
    }
    asm volatile("cp.async.commit_group;" ::: "memory");
    asm volatile("cp.async.wait_group 0;" ::: "memory");
    __syncthreads();

    bool act = (t < 104);
    int oh = t & 1, g = t >> 1;
    int xq = act ? (g % 13) : 0, y = act ? (g / 13) : 0;
    int x0 = 4 * xq;
    ull acc[4][8];
#pragma unroll
    for (int p = 0; p < 4; p++)
#pragma unroll
        for (int j = 0; j < 8; j++) acc[p][j] = 0ULL;
    if (act) {
        for (int ic = 0; ic < 5; ic++) {
#pragma unroll
            for (int ky = 0; ky < 5; ky++) {
                const float4* rp =
                    (const float4*)&sIn[ic * 1188 + (2 * y + ky) * 108 + 8 * xq];
                float4 q0 = rp[0], q1 = rp[1], q2 = rp[2];
                float in[12] = {q0.x, q0.y, q0.z, q0.w, q1.x, q1.y, q1.z, q1.w,
                                q2.x, q2.y, q2.z, q2.w};
                ull vp[11];
#pragma unroll
                for (int i = 0; i < 11; i++) vp[i] = pk2(in[i], in[i]);
                int kb = ic * 25 + ky * 5;
#pragma unroll
                for (int kx = 0; kx < 5; kx++) {
                    const ulonglong2* wr =
                        (const ulonglong2*)&sW[(kb + kx) * 32 + oh * 16];
                    ulonglong2 u0 = wr[0], u1 = wr[1], u2 = wr[2], u3 = wr[3];
                    ull w[8] = {u0.x, u0.y, u1.x, u1.y, u2.x, u2.y, u3.x, u3.y};
#pragma unroll
                    for (int p = 0; p < 4; p++) {
                        ull v = vp[2 * p + kx];
#pragma unroll
                        for (int j = 0; j < 8; j++)
                            acc[p][j] = fma2(v, w[j], acc[p][j]);
                    }
                }
            }
        }
    }
    int orow = 4 * tile + y;
    float q[32];
#pragma unroll
    for (int j = 0; j < 8; j++) {
        float lo[4], hi[4];
#pragma unroll
        for (int p = 0; p < 4; p++) upk2(acc[p][j], lo[p], hi[p]);
        int oc = 2 * (oh * 8 + j);
        float4 vlo = make_float4(lo[0], lo[1], lo[2], lo[3]);
        float4 vhi = make_float4(hi[0], hi[1], hi[2], hi[3]);
        if (act) {
            *(float4*)&g_y1[(b * 32 + oc) * 2704 + orow * 52 + x0] = vlo;
            *(float4*)&g_y1[(b * 32 + oc + 1) * 2704 + orow * 52 + x0] = vhi;
        }
        q[4 * j + 0] = vlo.x + vlo.y + vlo.z + vlo.w;
        q[4 * j + 1] = fmaf(vlo.x, vlo.x, fmaf(vlo.y, vlo.y,
                       fmaf(vlo.z, vlo.z, vlo.w * vlo.w)));
        q[4 * j + 2] = vhi.x + vhi.y + vhi.z + vhi.w;
        q[4 * j + 3] = fmaf(vhi.x, vhi.x, fmaf(vhi.y, vhi.y,
                       fmaf(vhi.z, vhi.z, vhi.w * vhi.w)));
    }
    int lane = t & 31, wid = t >> 5;
#pragma unroll
    for (int k = 0; k < 32; k++) {
        float v = q[k];
#pragma unroll
        for (int o = 16; o >= 2; o >>= 1) v += __shfl_down_sync(0xffffffffu, v, o);
        if (lane < 2) sRed[wid * 64 + lane * 32 + k] = v;   // lane == oh
    }
    __syncthreads();
    if (t < 64) {
        float tot = sRed[t] + sRed[64 + t] + sRed[128 + t] + sRed[192 + t];
        int ohh = t >> 5, k = t & 31;
        int c = 2 * (ohh * 8 + (k >> 2)) + ((k & 3) >> 1);
        if (k & 1) atomicAdd(&g_sq1[c], (double)tot);
        else       atomicAdd(&g_sum1[c], (double)tot);
    }
}

// ---------------- K2: BN1 finalize + apply (y1 -> y1n, col51 zeroed), float4 ----
__global__ void bnapply1_kernel(const float* __restrict__ g1,
                                const float* __restrict__ b1) {
    __shared__ float ss[32], ssh[32];
    int t = threadIdx.x;
    if (t < 32) {
        double N = 64.0 * 2704.0;
        double m = g_sum1[t] / N;
        double var = g_sq1[t] / N - m * m;
        float sc = g1[t] * (float)(1.0 / sqrt(var + (double)EPS));
        ss[t] = sc;
        ssh[t] = b1[t] - (float)m * sc;
    }
    __syncthreads();
    int i4 = blockIdx.x * 256 + t;                  // <<<5408,256>>> exact
    int idx = i4 * 4;
    int c = (idx / 2704) & 31;
    float sc = ss[c], sh = ssh[c];
    float4 v = *(const float4*)&g_y1[idx];
    float4 r;
    r.x = leaky(fmaf(v.x, sc, sh));
    r.y = leaky(fmaf(v.y, sc, sh));
    r.z = leaky(fmaf(v.z, sc, sh));
    r.w = (i4 % 13 == 12) ? 0.f : leaky(fmaf(v.w, sc, sh));
    *(float4*)&g_y1n[idx] = r;
}

// ---------------- K3: conv2 (cp.async, 4 ic per stage -> 8 barriers) -----------
// grid (4 ocg, 64 b), block 288. Thread: 4 px * 8 oc (oh = t&1 picks 8-oc half).
// Dynamic smem (floats): [0,21216)  input 2buf x 4plane x 2652
//                        [21216,24416) weights 2buf x 4plane x 400
//                        [24416,24704) sRed
#define CONV2_SMEM_BYTES (24704 * 4)
__global__ __launch_bounds__(288, 2) void conv2_kernel() {
    extern __shared__ __align__(16) float dsm[];
    int ocg = blockIdx.x, b = blockIdx.y, t = threadIdx.x;
    int oh = t & 1, pxg = t >> 1;
    int xg = pxg % 6, y = pxg / 6;
    int x0 = xg * 4;
    uint32_t smem_base;
    asm("{ .reg .u64 tmp; cvta.to.shared.u64 tmp, %1; cvt.u32.u64 %0, tmp; }"
        : "=r"(smem_base) : "l"(dsm));
    // loader: 3052 float4/stage (4 input planes 4x663; weights 4x100)
    const float* src[11];
    uint32_t dstoff[11];
    int stepf[11], bufmul[11];
    bool actv[11];
#pragma unroll
    for (int k = 0; k < 11; k++) {
        int j = t + k * 288;
        actv[k] = (j < 3052);
        if (j < 2652) {                     // input: 4 planes x 663 float4
            int plane = j / 663;
            int off = j - plane * 663;
            src[k] = g_y1n + (size_t)b * 86528 + plane * 2704 + off * 4;
            dstoff[k] = plane * 2652 + off * 4;
            stepf[k] = 10816;               // 4 planes per stage
            bufmul[k] = 10608;
        } else if (j < 3052) {              // weights: 4 x 100 float4
            int w = j - 2652;
            int plane = w / 100;
            int wi = w - plane * 100;
            src[k] = g_w2t + (plane * 25 + (wi >> 2)) * 64 + ocg * 16 + (wi & 3) * 4;
            dstoff[k] = 21216 + plane * 400 + wi * 4;
            stepf[k] = 6400;
            bufmul[k] = 1600;
        }
    }
#pragma unroll
    for (int k = 0; k < 11; k++)
        if (actv[k]) {
            uint32_t d = smem_base + dstoff[k] * 4;
            asm volatile("cp.async.cg.shared.global [%0], [%1], 16;"
                         :: "r"(d), "l"(src[k]) : "memory");
            src[k] += stepf[k];
        }
    asm volatile("cp.async.commit_group;" ::: "memory");

    ull acc[4][4];
#pragma unroll
    for (int p = 0; p < 4; p++)
#pragma unroll
        for (int j = 0; j < 4; j++) acc[p][j] = 0ULL;

    for (int s = 0; s < 8; s++) {
        int buf = s & 1;
        asm volatile("cp.async.wait_group 0;" ::: "memory");
        __syncthreads();
        if (s < 7) {
            int nb = buf ^ 1;
#pragma unroll
            for (int k = 0; k < 11; k++)
                if (actv[k]) {
                    uint32_t d = smem_base + (dstoff[k] + nb * bufmul[k]) * 4;
                    asm volatile("cp.async.cg.shared.global [%0], [%1], 16;"
                                 :: "r"(d), "l"(src[k]) : "memory");
                    src[k] += stepf[k];
                }
            asm volatile("cp.async.commit_group;" ::: "memory");
        }
#pragma unroll
        for (int q = 0; q < 4; q++) {
            int ibase = buf * 10608 + q * 2652;
            int wbase = 21216 + buf * 1600 + q * 400;
#pragma unroll
            for (int ky = 0; ky < 5; ky++) {
                const float4* rp =
                    (const float4*)&dsm[ibase + (2 * y + ky) * 52 + 8 * xg];
                float4 q0 = rp[0], q1 = rp[1], q2 = rp[2];
                float in[12] = {q0.x, q0.y, q0.z, q0.w, q1.x, q1.y, q1.z, q1.w,
                                q2.x, q2.y, q2.z, q2.w};
                ull vp[11];
#pragma unroll
                for (int i = 0; i < 11; i++) vp[i] = pk2(in[i], in[i]);
#pragma unroll
                for (int kx = 0; kx < 5; kx++) {
                    const ulonglong2* wr =
                        (const ulonglong2*)&dsm[wbase + (ky * 5 + kx) * 16 + oh * 8];
                    ulonglong2 u0 = wr[0], u1 = wr[1];
#pragma unroll
                    for (int p = 0; p < 4; p++) {
                        ull v = vp[2 * p + kx];
                        acc[p][0] = fma2(v, u0.x, acc[p][0]);
                        acc[p][1] = fma2(v, u0.y, acc[p][1]);
                        acc[p][2] = fma2(v, u1.x, acc[p][2]);
                        acc[p][3] = fma2(v, u1.y, acc[p][3]);
                    }
                }
            }
        }
    }
    // epilogue: float4 stores + fused BN2 raw stats
    float* sRed = &dsm[24416];
    float qv[16];
#pragma unroll
    for (int j = 0; j < 4; j++) {
        float lo[4], hi[4];
#pragma unroll
        for (int p = 0; p < 4; p++) upk2(acc[p][j], lo[p], hi[p]);
        int oc = ocg * 16 + oh * 8 + 2 * j;
        float4 vlo = make_float4(lo[0], lo[1], lo[2], lo[3]);
        float4 vhi = make_float4(hi[0], hi[1], hi[2], hi[3]);
        *(float4*)&g_y2[(b * 64 + oc) * 576 + y * 24 + x0] = vlo;
        *(float4*)&g_y2[(b * 64 + oc + 1) * 576 + y * 24 + x0] = vhi;
        qv[4 * j + 0] = vlo.x + vlo.y + vlo.z + vlo.w;
        qv[4 * j + 1] = fmaf(vlo.x, vlo.x, fmaf(vlo.y, vlo.y,
                        fmaf(vlo.z, vlo.z, vlo.w * vlo.w)));
        qv[4 * j + 2] = vhi.x + vhi.y + vhi.z + vhi.w;
        qv[4 * j + 3] = fmaf(vhi.x, vhi.x, fmaf(vhi.y, vhi.y,
                        fmaf(vhi.z, vhi.z, vhi.w * vhi.w)));
    }
    int lane = t & 31, wid = t >> 5;
#pragma unroll
    for (int k = 0; k < 16; k++) {
        float v = qv[k];
#pragma unroll
        for (int o = 16; o >= 2; o >>= 1) v += __shfl_down_sync(0xffffffffu, v, o);
        if (lane < 2) sRed[wid * 32 + lane * 16 + k] = v;   // lane == oh
    }
    __syncthreads();
    if (t < 32) {
        float tot = 0.f;
#pragma unroll
        for (int w = 0; w < 9; w++) tot += sRed[w * 32 + t];
        int ohh = t >> 4, k = t & 15;
        int oc = ocg * 16 + ohh * 8 + 2 * (k >> 2) + ((k >> 1) & 1);
        if (k & 1) atomicAdd(&g_sq2[oc], (double)tot);
        else       atomicAdd(&g_sum2[oc], (double)tot);
    }
}

// ---------------- K4: fc1 GEMM (BN2 finalize+apply fused), split-K atomics ------
// grid (2 n-tiles of 256, 144 k-splits of 256), 256 thr. Thread: 8b x 8j.
__global__ __launch_bounds__(256, 2) void fc1_kernel(
    const float* __restrict__ W, const float* __restrict__ g2,
    const float* __restrict__ b2) {
    __shared__ __align__(16) float sX[2][16 * 64];
    __shared__ __align__(16) float sW[2][16 * 256];
    __shared__ float sS2[64], sSh2[64];
    int n0 = blockIdx.x * 256, k0 = blockIdx.y * 256, t = threadIdx.x;
    if (t < 64) {
        double N = 64.0 * 576.0;
        double m = g_sum2[t] / N;
        double var = g_sq2[t] / N - m * m;
        float sc = g2[t] * (float)(1.0 / sqrt(var + (double)EPS));
        sS2[t] = sc;
        sSh2[t] = b2[t] - (float)m * sc;
    }
    __syncthreads();
    int bgrp = t >> 5, c = t & 31, b0 = bgrp * 8, c4 = c * 4;
    int xb = t >> 2, xks = (t & 3) * 4;
    const float* wrow = &W[(size_t)(n0 + t) * 36864];
    {
        int kidx = k0 + xks;
        int ch = kidx / 576;
        float sc = sS2[ch], sh = sSh2[ch];
        float4 q0 = *(const float4*)&g_y2[xb * 36864 + kidx];
        float tmp[4] = {q0.x, q0.y, q0.z, q0.w};
#pragma unroll
        for (int i = 0; i < 4; i++)
            sX[0][(xks + i) * 64 + xb] = leaky(fmaf(tmp[i], sc, sh));
        const float4* ws = (const float4*)&wrow[k0];
        float4 w0 = ws[0], w1 = ws[1], w2v = ws[2], w3 = ws[3];
        float tw[16] = {w0.x, w0.y, w0.z, w0.w, w1.x, w1.y, w1.z, w1.w,
                        w2v.x, w2v.y, w2v.z, w2v.w, w3.x, w3.y, w3.z, w3.w};
#pragma unroll
        for (int i = 0; i < 16; i++) sW[0][i * 256 + t] = tw[i];
    }
    __syncthreads();
    ull acc[4][8];
#pragma unroll
    for (int i = 0; i < 4; i++)
#pragma unroll
        for (int j = 0; j < 8; j++) acc[i][j] = 0ULL;
    for (int kt = 0; kt < 16; kt++) {
        int cur = kt & 1, nxt = cur ^ 1;
        float xr[4], wr2[16], scn = 0.f, shn = 0.f;
        if (kt < 15) {
            int kb = k0 + (kt + 1) * 16;
            int kidx = kb + xks;
            int ch = kidx / 576;
            scn = sS2[ch];
            shn = sSh2[ch];
            float4 q0 = *(const float4*)&g_y2[xb * 36864 + kidx];
            xr[0] = q0.x; xr[1] = q0.y; xr[2] = q0.z; xr[3] = q0.w;
            const float4* ws = (const float4*)&wrow[kb];
            float4 w0 = ws[0], w1 = ws[1], w2v = ws[2], w3 = ws[3];
            wr2[0] = w0.x;  wr2[1] = w0.y;  wr2[2] = w0.z;  wr2[3] = w0.w;
            wr2[4] = w1.x;  wr2[5] = w1.y;  wr2[6] = w1.z;  wr2[7] = w1.w;
            wr2[8] = w2v.x; wr2[9] = w2v.y; wr2[10] = w2v.z; wr2[11] = w2v.w;
            wr2[12] = w3.x; wr2[13] = w3.y; wr2[14] = w3.z; wr2[15] = w3.w;
        }
#pragma unroll
        for (int kk = 0; kk < 16; kk++) {
            const ulonglong2* xrp = (const ulonglong2*)&sX[cur][kk * 64 + b0];
            ulonglong2 x01 = xrp[0], x23 = xrp[1];
            ull xp[4] = {x01.x, x01.y, x23.x, x23.y};
            float4 wa = *(const float4*)&sW[cur][kk * 256 + c4];
            float4 wb = *(const float4*)&sW[cur][kk * 256 + 128 + c4];
            ull w[8] = {pk2(wa.x, wa.x), pk2(wa.y, wa.y),
                        pk2(wa.z, wa.z), pk2(wa.w, wa.w),
                        pk2(wb.x, wb.x), pk2(wb.y, wb.y),
                        pk2(wb.z, wb.z), pk2(wb.w, wb.w)};
#pragma unroll
            for (int j = 0; j < 8; j++)
#pragma unroll
                for (int bp = 0; bp < 4; bp++)
                    acc[bp][j] = fma2(xp[bp], w[j], acc[bp][j]);
        }
        if (kt < 15) {
#pragma unroll
            for (int i = 0; i < 4; i++)
                sX[nxt][(xks + i) * 64 + xb] = leaky(fmaf(xr[i], scn, shn));
#pragma unroll
            for (int i = 0; i < 16; i++) sW[nxt][i * 256 + t] = wr2[i];
        }
        __syncthreads();
    }
#pragma unroll
    for (int j = 0; j < 8; j++) {
        int jj = n0 + ((j < 4) ? (c4 + j) : (128 + c4 + j - 4));
#pragma unroll
        for (int bp = 0; bp < 4; bp++) {
            float l, h;
            upk2(acc[bp][j], l, h);
            atomicAdd(&g_fc1[(b0 + 2 * bp) * 512 + jj], l);
            atomicAdd(&g_fc1[(b0 + 2 * bp + 1) * 512 + jj], h);
        }
    }
}

// ---------------- K5: fused BN3 stats + BN3 apply + fc2 + sigmoid ----------------
__global__ void final_kernel(const float* __restrict__ g3, const float* __restrict__ b3,
                             const float* __restrict__ w2, const float* __restrict__ b2,
                             float* __restrict__ out) {
    __shared__ float s3[512], sh3[512];
    int b = blockIdx.x, t = threadIdx.x;   // <<<64,256>>>
    for (int j = t; j < 512; j += 256) {
        float s1 = 0.f, s2 = 0.f;
#pragma unroll 8
        for (int bb = 0; bb < 64; bb++) {
            float v = g_fc1[bb * 512 + j];
            s1 += v;
            s2 = fmaf(v, v, s2);
        }
        double m = (double)s1 / 64.0, var = (double)s2 / 64.0 - m * m;
        float sc = g3[j] * (float)(1.0 / sqrt(var + (double)EPS));
        s3[j] = sc;
        sh3[j] = b3[j] - (float)m * sc;
    }
    __syncthreads();
    float s = 0.f;
    for (int j = t; j < 512; j += 256) {
        float v = leaky(fmaf(g_fc1[b * 512 + j], s3[j], sh3[j]));
        s += v * w2[j];
    }
    __shared__ float red[256];
    red[t] = s;
    __syncthreads();
    for (int o = 128; o > 0; o >>= 1) {
        if (t < o) red[t] += red[t + o];
        __syncthreads();
    }
    if (t == 0) {
        float z = red[0] + b2[0];
        out[b] = 1.f / (1.f + expf(-z));
    }
}

// ---------------- launch ----------------
extern "C" void kernel_launch(void* const* d_in, const int* in_sizes, int n_in,
                              void* d_out, int out_size) {
    const float* image   = (const float*)d_in[0];
    const float* conv1_w = (const float*)d_in[1];
    const float* bn1_g   = (const float*)d_in[3];
    const float* bn1_b   = (const float*)d_in[4];
    const float* conv2_w = (const float*)d_in[5];
    const float* bn2_g   = (const float*)d_in[7];
    const float* bn2_b   = (const float*)d_in[8];
    const float* fc1_w   = (const float*)d_in[9];
    const float* bn3_g   = (const float*)d_in[11];
    const float* bn3_b   = (const float*)d_in[12];
    const float* fc2_w   = (const float*)d_in[13];
    const float* fc2_b   = (const float*)d_in[14];
    float* out = (float*)d_out;

    static bool attr_done = false;
    if (!attr_done) {
        cudaFuncSetAttribute(conv2_kernel,
                             cudaFuncAttributeMaxDynamicSharedMemorySize,
                             CONV2_SMEM_BYTES);
        attr_done = true;
    }

    layout_kernel<<<dim3(46, 64), 256>>>(image, conv2_w, conv1_w);  // idx 0
    conv1_kernel<<<dim3(13, 64), 128>>>();                          // idx 1
    bnapply1_kernel<<<5408, 256>>>(bn1_g, bn1_b);                   // idx 2
    conv2_kernel<<<dim3(4, 64), 288, CONV2_SMEM_BYTES>>>();         // idx 3 (profiled)
    fc1_kernel<<<dim3(2, 144), 256>>>(fc1_w, bn2_g, bn2_b);         // idx 4
    final_kernel<<<64, 256>>>(bn3_g, bn3_b, fc2_w, fc2_b, out);     // idx 5
}

// round 17
// speedup vs baseline: 1.0583x; 1.0583x over previous
#include <cuda_runtime.h>
#include <math.h>
#include <stdint.h>

#define EPS 1e-5f
typedef unsigned long long ull;

// ---------------- persistent scratch ----------------
__device__ float g_layout[64 * 5 * 108 * 108];
__device__ float g_y1[64 * 32 * 52 * 52];        // conv1 raw out
__device__ float g_y1n[64 * 32 * 52 * 52];       // BN1+leaky applied, col51 zeroed
__device__ float g_w1t[125 * 32];                // conv1 weights [k=125][oc=32]
__device__ float g_w2t[32 * 25 * 64];            // conv2 weights [ic][kk][oc]
__device__ float g_y2[64 * 64 * 24 * 24];
__device__ float g_fc1[64 * 512];
__device__ double g_sum1[32], g_sq1[32];
__device__ double g_sum2[64], g_sq2[64];

// ---------------- f32x2 helpers ----------------
__device__ __forceinline__ ull fma2(ull a, ull b, ull c) {
    ull d;
    asm("fma.rn.f32x2 %0, %1, %2, %3;" : "=l"(d) : "l"(a), "l"(b), "l"(c));
    return d;
}
__device__ __forceinline__ ull pk2(float a, float b) {
    ull r;
    asm("mov.b64 %0, {%1, %2};" : "=l"(r) : "f"(a), "f"(b));
    return r;
}
__device__ __forceinline__ void upk2(ull v, float& a, float& b) {
    asm("mov.b64 {%0, %1}, %2;" : "=f"(a), "=f"(b) : "l"(v));
}
__device__ __forceinline__ float leaky(float v) { return v > 0.f ? v : 0.2f * v; }

// ---------------- K0: layout render (+ zeros + weight transposes) --------------
__global__ void layout_kernel(const float* __restrict__ img,
                              const float* __restrict__ w2,
                              const float* __restrict__ w1) {
    int b = blockIdx.y, t = threadIdx.x;
    int bid = b * 46 + blockIdx.x;
    if (bid < 128) g_fc1[bid * 256 + t] = 0.f;
    if (bid == 0) {
        if (t < 32) { g_sum1[t] = 0.0; g_sq1[t] = 0.0; }
        else if (t < 96) { g_sum2[t - 32] = 0.0; g_sq2[t - 32] = 0.0; }
    }
    if (bid < 200) {   // transpose conv2 weights: w2t[(ic*25+kk)*64+oc]
        int idx = bid * 256 + t;           // < 51200
        int oc = idx & 63, r = idx >> 6;
        int ic = r / 25, kk = r - 25 * ic;
        g_w2t[idx] = w2[(oc * 32 + ic) * 25 + kk];
    } else if (bid < 216) {  // transpose conv1 weights: w1t[k*32+oc]
        int idx = (bid - 200) * 256 + t;   // < 4096
        if (idx < 4000) {
            int oc = idx & 31, k = idx >> 5;
            g_w1t[idx] = w1[oc * 125 + k];
        }
    }
    __shared__ float so[81];
    if (t < 81) so[t] = img[b * 81 + t];
    __syncthreads();
    int p = blockIdx.x * 256 + t;
    if (p >= 11664) return;
    int y = p / 108, x = p - y * 108;
    float fx = (float)x, fy = (float)y;
    float m[5];
#pragma unroll
    for (int c = 0; c < 5; c++) m[c] = -3.4e38f;
#pragma unroll
    for (int o = 0; o < 9; o++) {
        const float* f = &so[o * 9];
        float xc = f[0] * 108.f, yc = f[1] * 108.f;
        float hw = f[2] * 54.f, hh = f[3] * 54.f;
        float x1 = xc - hw, x2 = xc + hw, y1 = yc - hh, y2 = yc + hh;
        float x1d = fx - x1, x2d = x2 - fx, y1d = fy - y1, y2d = y2 - fy;
        float yin = __saturatef(y1d) * __saturatef(y2d);
        float xin = __saturatef(x1d) * __saturatef(x2d);
        float l1 = fmaxf(1.f - fabsf(x1d), 0.f) * yin;
        float l2 = fmaxf(1.f - fabsf(x2d), 0.f) * yin;
        float l3 = fmaxf(1.f - fabsf(y1d), 0.f) * xin;
        float l4 = fmaxf(1.f - fabsf(y2d), 0.f) * xin;
        float xym = fmaxf(fmaxf(l1, l2), fmaxf(l3, l4));
#pragma unroll
        for (int c = 0; c < 5; c++) m[c] = fmaxf(m[c], xym * f[4 + c]);
    }
#pragma unroll
    for (int c = 0; c < 5; c++) g_layout[(b * 5 + c) * 11664 + p] = m[c];
}

// ---------------- K1: conv1 + fused BN1 raw stats (cp.async loads) -------------
// grid (13, 64), block 128 (104 active). Thread: 4 consecutive px * 16 oc (oh half).
__global__ __launch_bounds__(128, 4) void conv1_kernel() {
    __shared__ __align__(16) float sW[4000];        // [k=125][oc=32]
    __shared__ __align__(16) float sIn[5940];       // 5 ch x 11 rows x 108
    __shared__ float sRed[4 * 64];
    int b = blockIdx.y, tile = blockIdx.x, t = threadIdx.x;
    int r0 = 8 * tile;
    uint32_t sIn_b, sW_b;
    asm("{ .reg .u64 tmp; cvta.to.shared.u64 tmp, %1; cvt.u32.u64 %0, tmp; }"
        : "=r"(sIn_b) : "l"(sIn));
    asm("{ .reg .u64 tmp; cvta.to.shared.u64 tmp, %1; cvt.u32.u64 %0, tmp; }"
        : "=r"(sW_b) : "l"(sW));
#pragma unroll
    for (int k = 0; k < 20; k++) {
        int j = t + k * 128;
        if (j < 1485) {
            int ic = j / 297, off = j - ic * 297;
            const float* g = g_layout + (size_t)(b * 5 + ic) * 11664
                             + r0 * 108 + off * 4;
            uint32_t d = sIn_b + (ic * 1188 + off * 4) * 4;
            asm volatile("cp.async.cg.shared.global [%0], [%1], 16;"
                         :: "r"(d), "l"(g) : "memory");
        } else if (j < 2485) {
            int wj = j - 1485;
            const float* g = g_w1t + wj * 4;
            uint32_t d = sW_b + wj * 16;
            asm volatile("cp.async.cg.shared.global [%0], [%1], 16;"
                         :: "r"(d), "l"(g) : "memory");
        }
    }
    asm volatile("cp.async.commit_group;" ::: "memory");
    asm volatile("cp.async.wait_group 0;" ::: "memory");
    __syncthreads();

    bool act = (t < 104);
    int oh = t & 1, g = t >> 1;
    int xq = act ? (g % 13) : 0, y = act ? (g / 13) : 0;
    int x0 = 4 * xq;
    ull acc[4][8];
#pragma unroll
    for (int p = 0; p < 4; p++)
#pragma unroll
        for (int j = 0; j < 8; j++) acc[p][j] = 0ULL;
    if (act) {
        for (int ic = 0; ic < 5; ic++) {
#pragma unroll
            for (int ky = 0; ky < 5; ky++) {
                const float4* rp =
                    (const float4*)&sIn[ic * 1188 + (2 * y + ky) * 108 + 8 * xq];
                float4 q0 = rp[0], q1 = rp[1], q2 = rp[2];
                float in[12] = {q0.x, q0.y, q0.z, q0.w, q1.x, q1.y, q1.z, q1.w,
                                q2.x, q2.y, q2.z, q2.w};
                ull vp[11];
#pragma unroll
                for (int i = 0; i < 11; i++) vp[i] = pk2(in[i], in[i]);
                int kb = ic * 25 + ky * 5;
#pragma unroll
                for (int kx = 0; kx < 5; kx++) {
                    const ulonglong2* wr =
                        (const ulonglong2*)&sW[(kb + kx) * 32 + oh * 16];
                    ulonglong2 u0 = wr[0], u1 = wr[1], u2 = wr[2], u3 = wr[3];
                    ull w[8] = {u0.x, u0.y, u1.x, u1.y, u2.x, u2.y, u3.x, u3.y};
#pragma unroll
                    for (int p = 0; p < 4; p++) {
                        ull v = vp[2 * p + kx];
#pragma unroll
                        for (int j = 0; j < 8; j++)
                            acc[p][j] = fma2(v, w[j], acc[p][j]);
                    }
                }
            }
        }
    }
    int orow = 4 * tile + y;
    float q[32];
#pragma unroll
    for (int j = 0; j < 8; j++) {
        float lo[4], hi[4];
#pragma unroll
        for (int p = 0; p < 4; p++) upk2(acc[p][j], lo[p], hi[p]);
        int oc = 2 * (oh * 8 + j);
        float4 vlo = make_float4(lo[0], lo[1], lo[2], lo[3]);
        float4 vhi = make_float4(hi[0], hi[1], hi[2], hi[3]);
        if (act) {
            *(float4*)&g_y1[(b * 32 + oc) * 2704 + orow * 52 + x0] = vlo;
            *(float4*)&g_y1[(b * 32 + oc + 1) * 2704 + orow * 52 + x0] = vhi;
        }
        q[4 * j + 0] = vlo.x + vlo.y + vlo.z + vlo.w;
        q[4 * j + 1] = fmaf(vlo.x, vlo.x, fmaf(vlo.y, vlo.y,
                       fmaf(vlo.z, vlo.z, vlo.w * vlo.w)));
        q[4 * j + 2] = vhi.x + vhi.y + vhi.z + vhi.w;
        q[4 * j + 3] = fmaf(vhi.x, vhi.x, fmaf(vhi.y, vhi.y,
                       fmaf(vhi.z, vhi.z, vhi.w * vhi.w)));
    }
    int lane = t & 31, wid = t >> 5;
#pragma unroll
    for (int k = 0; k < 32; k++) {
        float v = q[k];
#pragma unroll
        for (int o = 16; o >= 2; o >>= 1) v += __shfl_down_sync(0xffffffffu, v, o);
        if (lane < 2) sRed[wid * 64 + lane * 32 + k] = v;   // lane == oh
    }
    __syncthreads();
    if (t < 64) {
        float tot = sRed[t] + sRed[64 + t] + sRed[128 + t] + sRed[192 + t];
        int ohh = t >> 5, k = t & 31;
        int c = 2 * (ohh * 8 + (k >> 2)) + ((k & 3) >> 1);
        if (k & 1) atomicAdd(&g_sq1[c], (double)tot);
        else       atomicAdd(&g_sum1[c], (double)tot);
    }
}

// ---------------- K2: BN1 finalize + apply (y1 -> y1n, col51 zeroed), float4 ----
__global__ void bnapply1_kernel(const float* __restrict__ g1,
                                const float* __restrict__ b1) {
    __shared__ float ss[32], ssh[32];
    int t = threadIdx.x;
    if (t < 32) {
        double N = 64.0 * 2704.0;
        double m = g_sum1[t] / N;
        double var = g_sq1[t] / N - m * m;
        float sc = g1[t] * (float)(1.0 / sqrt(var + (double)EPS));
        ss[t] = sc;
        ssh[t] = b1[t] - (float)m * sc;
    }
    __syncthreads();
    int i4 = blockIdx.x * 256 + t;                  // <<<5408,256>>> exact
    int idx = i4 * 4;
    int c = (idx / 2704) & 31;
    float sc = ss[c], sh = ssh[c];
    float4 v = *(const float4*)&g_y1[idx];
    float4 r;
    r.x = leaky(fmaf(v.x, sc, sh));
    r.y = leaky(fmaf(v.y, sc, sh));
    r.z = leaky(fmaf(v.z, sc, sh));
    r.w = (i4 % 13 == 12) ? 0.f : leaky(fmaf(v.w, sc, sh));
    *(float4*)&g_y1n[idx] = r;
}

// ---------------- K3: conv2, 32 oc/block (ocq=t&3), grid (2,64) ----------------
// Block 576 thr: pxg = t>>2 (xg=pxg%6, y=pxg/6), ocq = t&3 picks 8-oc octet.
// Input LDGSTS per FMA halves vs 16-oc blocks; warp input LDS has 8 distinct addrs.
// Dynamic smem (floats): [0,10608)  input 2buf x 2plane x 2652
//                        [10608,13808) weights 2buf x 2plane x 800 ([kk][32oc])
//                        [13808,14960) sRed (18 warps x 64)
#define CONV2_SMEM_BYTES (14960 * 4)
__global__ __launch_bounds__(576, 1) void conv2_kernel() {
    extern __shared__ __align__(16) float dsm[];
    int ocg = blockIdx.x, b = blockIdx.y, t = threadIdx.x;
    int ocq = t & 3, pxg = t >> 2;
    int xg = pxg % 6, y = pxg / 6;
    int x0 = xg * 4;
    uint32_t smem_base;
    asm("{ .reg .u64 tmp; cvta.to.shared.u64 tmp, %1; cvt.u32.u64 %0, tmp; }"
        : "=r"(smem_base) : "l"(dsm));
    // loader: 1726 float4/stage (input 2x663; weights 2x200) -> 3 jobs/thread
    const float* src[3];
    uint32_t dstoff[3];
    int stepf[3], bufmul[3];
    bool actv[3];
#pragma unroll
    for (int k = 0; k < 3; k++) {
        int j = t + k * 576;
        actv[k] = (j < 1726);
        if (j < 1326) {                     // input planes: 2 x 663 float4
            int plane = (j >= 663) ? 1 : 0;
            int off = j - plane * 663;
            src[k] = g_y1n + (size_t)b * 86528 + plane * 2704 + off * 4;
            dstoff[k] = plane * 2652 + off * 4;
            stepf[k] = 5408;
            bufmul[k] = 5304;
        } else if (j < 1726) {              // weights: 2 x 200 float4 ([kk][32oc])
            int w = j - 1326;
            int plane = (w >= 200) ? 1 : 0;
            int wi = w - plane * 200;       // [0,200): kk = wi>>3, oc4 = wi&7
            src[k] = g_w2t + (plane * 25 + (wi >> 3)) * 64 + ocg * 32 + (wi & 7) * 4;
            dstoff[k] = 10608 + plane * 800 + wi * 4;
            stepf[k] = 3200;
            bufmul[k] = 1600;
        }
    }
#pragma unroll
    for (int k = 0; k < 3; k++)
        if (actv[k]) {
            uint32_t d = smem_base + dstoff[k] * 4;
            asm volatile("cp.async.cg.shared.global [%0], [%1], 16;"
                         :: "r"(d), "l"(src[k]) : "memory");
            src[k] += stepf[k];
        }
    asm volatile("cp.async.commit_group;" ::: "memory");

    ull acc[4][4];
#pragma unroll
    for (int p = 0; p < 4; p++)
#pragma unroll
        for (int j = 0; j < 4; j++) acc[p][j] = 0ULL;

    for (int s = 0; s < 16; s++) {
        int buf = s & 1;
        asm volatile("cp.async.wait_group 0;" ::: "memory");
        __syncthreads();
        if (s < 15) {
            int nb = buf ^ 1;
#pragma unroll
            for (int k = 0; k < 3; k++)
                if (actv[k]) {
                    uint32_t d = smem_base + (dstoff[k] + nb * bufmul[k]) * 4;
                    asm volatile("cp.async.cg.shared.global [%0], [%1], 16;"
                                 :: "r"(d), "l"(src[k]) : "memory");
                    src[k] += stepf[k];
                }
            asm volatile("cp.async.commit_group;" ::: "memory");
        }
#pragma unroll
        for (int q = 0; q < 2; q++) {
            int ibase = buf * 5304 + q * 2652;
            int wbase = 10608 + buf * 1600 + q * 800;
#pragma unroll
            for (int ky = 0; ky < 5; ky++) {
                const float4* rp =
                    (const float4*)&dsm[ibase + (2 * y + ky) * 52 + 8 * xg];
                float4 q0 = rp[0], q1 = rp[1], q2 = rp[2];
                float in[12] = {q0.x, q0.y, q0.z, q0.w, q1.x, q1.y, q1.z, q1.w,
                                q2.x, q2.y, q2.z, q2.w};
                ull vp[11];
#pragma unroll
                for (int i = 0; i < 11; i++) vp[i] = pk2(in[i], in[i]);
#pragma unroll
                for (int kx = 0; kx < 5; kx++) {
                    const ulonglong2* wr =
                        (const ulonglong2*)&dsm[wbase + (ky * 5 + kx) * 32 + ocq * 8];
                    ulonglong2 u0 = wr[0], u1 = wr[1];
#pragma unroll
                    for (int p = 0; p < 4; p++) {
                        ull v = vp[2 * p + kx];
                        acc[p][0] = fma2(v, u0.x, acc[p][0]);
                        acc[p][1] = fma2(v, u0.y, acc[p][1]);
                        acc[p][2] = fma2(v, u1.x, acc[p][2]);
                        acc[p][3] = fma2(v, u1.y, acc[p][3]);
                    }
                }
            }
        }
    }
    // epilogue: float4 stores + fused BN2 raw stats (32 oc per block)
    float* sRed = &dsm[13808];
    float qv[16];
#pragma unroll
    for (int j = 0; j < 4; j++) {
        float lo[4], hi[4];
#pragma unroll
        for (int p = 0; p < 4; p++) upk2(acc[p][j], lo[p], hi[p]);
        int oc = ocg * 32 + ocq * 8 + 2 * j;
        float4 vlo = make_float4(lo[0], lo[1], lo[2], lo[3]);
        float4 vhi = make_float4(hi[0], hi[1], hi[2], hi[3]);
        *(float4*)&g_y2[(b * 64 + oc) * 576 + y * 24 + x0] = vlo;
        *(float4*)&g_y2[(b * 64 + oc + 1) * 576 + y * 24 + x0] = vhi;
        qv[4 * j + 0] = vlo.x + vlo.y + vlo.z + vlo.w;
        qv[4 * j + 1] = fmaf(vlo.x, vlo.x, fmaf(vlo.y, vlo.y,
                        fmaf(vlo.z, vlo.z, vlo.w * vlo.w)));
        qv[4 * j + 2] = vhi.x + vhi.y + vhi.z + vhi.w;
        qv[4 * j + 3] = fmaf(vhi.x, vhi.x, fmaf(vhi.y, vhi.y,
                        fmaf(vhi.z, vhi.z, vhi.w * vhi.w)));
    }
    int lane = t & 31, wid = t >> 5;
    // lanes with equal ocq are stride-4; reduce over the 8 pxg in the warp
#pragma unroll
    for (int k = 0; k < 16; k++) {
        float v = qv[k];
        v += __shfl_down_sync(0xffffffffu, v, 16);
        v += __shfl_down_sync(0xffffffffu, v, 8);
        v += __shfl_down_sync(0xffffffffu, v, 4);
        if (lane < 4) sRed[wid * 64 + lane * 16 + k] = v;   // lane == ocq
    }
    __syncthreads();
    if (t < 64) {
        int o = t >> 4, k = t & 15;
        float tot = 0.f;
#pragma unroll
        for (int w = 0; w < 18; w++) tot += sRed[w * 64 + o * 16 + k];
        int oc = ocg * 32 + o * 8 + 2 * (k >> 2) + ((k >> 1) & 1);
        if (k & 1) atomicAdd(&g_sq2[oc], (double)tot);
        else       atomicAdd(&g_sum2[oc], (double)tot);
    }
}

// ---------------- K4: fc1 GEMM (BN2 finalize+apply fused), split-K atomics ------
// grid (2 n-tiles of 256, 144 k-splits of 256), 256 thr. Thread: 8b x 8j.
__global__ __launch_bounds__(256, 2) void fc1_kernel(
    const float* __restrict__ W, const float* __restrict__ g2,
    const float* __restrict__ b2) {
    __shared__ __align__(16) float sX[2][16 * 64];
    __shared__ __align__(16) float sW[2][16 * 256];
    __shared__ float sS2[64], sSh2[64];
    int n0 = blockIdx.x * 256, k0 = blockIdx.y * 256, t = threadIdx.x;
    if (t < 64) {
        double N = 64.0 * 576.0;
        double m = g_sum2[t] / N;
        double var = g_sq2[t] / N - m * m;
        float sc = g2[t] * (float)(1.0 / sqrt(var + (double)EPS));
        sS2[t] = sc;
        sSh2[t] = b2[t] - (float)m * sc;
    }
    __syncthreads();
    int bgrp = t >> 5, c = t & 31, b0 = bgrp * 8, c4 = c * 4;
    int xb = t >> 2, xks = (t & 3) * 4;
    const float* wrow = &W[(size_t)(n0 + t) * 36864];
    {
        int kidx = k0 + xks;
        int ch = kidx / 576;
        float sc = sS2[ch], sh = sSh2[ch];
        float4 q0 = *(const float4*)&g_y2[xb * 36864 + kidx];
        float tmp[4] = {q0.x, q0.y, q0.z, q0.w};
#pragma unroll
        for (int i = 0; i < 4; i++)
            sX[0][(xks + i) * 64 + xb] = leaky(fmaf(tmp[i], sc, sh));
        const float4* ws = (const float4*)&wrow[k0];
        float4 w0 = ws[0], w1 = ws[1], w2v = ws[2], w3 = ws[3];
        float tw[16] = {w0.x, w0.y, w0.z, w0.w, w1.x, w1.y, w1.z, w1.w,
                        w2v.x, w2v.y, w2v.z, w2v.w, w3.x, w3.y, w3.z, w3.w};
#pragma unroll
        for (int i = 0; i < 16; i++) sW[0][i * 256 + t] = tw[i];
    }
    __syncthreads();
    ull acc[4][8];
#pragma unroll
    for (int i = 0; i < 4; i++)
#pragma unroll
        for (int j = 0; j < 8; j++) acc[i][j] = 0ULL;
    for (int kt = 0; kt < 16; kt++) {
        int cur = kt & 1, nxt = cur ^ 1;
        float xr[4], wr2[16], scn = 0.f, shn = 0.f;
        if (kt < 15) {
            int kb = k0 + (kt + 1) * 16;
            int kidx = kb + xks;
            int ch = kidx / 576;
            scn = sS2[ch];
            shn = sSh2[ch];
            float4 q0 = *(const float4*)&g_y2[xb * 36864 + kidx];
            xr[0] = q0.x; xr[1] = q0.y; xr[2] = q0.z; xr[3] = q0.w;
            const float4* ws = (const float4*)&wrow[kb];
            float4 w0 = ws[0], w1 = ws[1], w2v = ws[2], w3 = ws[3];
            wr2[0] = w0.x;  wr2[1] = w0.y;  wr2[2] = w0.z;  wr2[3] = w0.w;
            wr2[4] = w1.x;  wr2[5] = w1.y;  wr2[6] = w1.z;  wr2[7] = w1.w;
            wr2[8] = w2v.x; wr2[9] = w2v.y; wr2[10] = w2v.z; wr2[11] = w2v.w;
            wr2[12] = w3.x; wr2[13] = w3.y; wr2[14] = w3.z; wr2[15] = w3.w;
        }
#pragma unroll
        for (int kk = 0; kk < 16; kk++) {
            const ulonglong2* xrp = (const ulonglong2*)&sX[cur][kk * 64 + b0];
            ulonglong2 x01 = xrp[0], x23 = xrp[1];
            ull xp[4] = {x01.x, x01.y, x23.x, x23.y};
            float4 wa = *(const float4*)&sW[cur][kk * 256 + c4];
            float4 wb = *(const float4*)&sW[cur][kk * 256 + 128 + c4];
            ull w[8] = {pk2(wa.x, wa.x), pk2(wa.y, wa.y),
                        pk2(wa.z, wa.z), pk2(wa.w, wa.w),
                        pk2(wb.x, wb.x), pk2(wb.y, wb.y),
                        pk2(wb.z, wb.z), pk2(wb.w, wb.w)};
#pragma unroll
            for (int j = 0; j < 8; j++)
#pragma unroll
                for (int bp = 0; bp < 4; bp++)
                    acc[bp][j] = fma2(xp[bp], w[j], acc[bp][j]);
        }
        if (kt < 15) {
#pragma unroll
            for (int i = 0; i < 4; i++)
                sX[nxt][(xks + i) * 64 + xb] = leaky(fmaf(xr[i], scn, shn));
#pragma unroll
            for (int i = 0; i < 16; i++) sW[nxt][i * 256 + t] = wr2[i];
        }
        __syncthreads();
    }
#pragma unroll
    for (int j = 0; j < 8; j++) {
        int jj = n0 + ((j < 4) ? (c4 + j) : (128 + c4 + j - 4));
#pragma unroll
        for (int bp = 0; bp < 4; bp++) {
            float l, h;
            upk2(acc[bp][j], l, h);
            atomicAdd(&g_fc1[(b0 + 2 * bp) * 512 + jj], l);
            atomicAdd(&g_fc1[(b0 + 2 * bp + 1) * 512 + jj], h);
        }
    }
}

// ---------------- K5: fused BN3 stats + BN3 apply + fc2 + sigmoid ----------------
__global__ void final_kernel(const float* __restrict__ g3, const float* __restrict__ b3,
                             const float* __restrict__ w2, const float* __restrict__ b2,
                             float* __restrict__ out) {
    __shared__ float s3[512], sh3[512];
    int b = blockIdx.x, t = threadIdx.x;   // <<<64,256>>>
    for (int j = t; j < 512; j += 256) {
        float s1 = 0.f, s2 = 0.f;
#pragma unroll 8
        for (int bb = 0; bb < 64; bb++) {
            float v = g_fc1[bb * 512 + j];
            s1 += v;
            s2 = fmaf(v, v, s2);
        }
        double m = (double)s1 / 64.0, var = (double)s2 / 64.0 - m * m;
        float sc = g3[j] * (float)(1.0 / sqrt(var + (double)EPS));
        s3[j] = sc;
        sh3[j] = b3[j] - (float)m * sc;
    }
    __syncthreads();
    float s = 0.f;
    for (int j = t; j < 512; j += 256) {
        float v = leaky(fmaf(g_fc1[b * 512 + j], s3[j], sh3[j]));
        s += v * w2[j];
    }
    __shared__ float red[256];
    red[t] = s;
    __syncthreads();
    for (int o = 128; o > 0; o >>= 1) {
        if (t < o) red[t] += red[t + o];
        __syncthreads();
    }
    if (t == 0) {
        float z = red[0] + b2[0];
        out[b] = 1.f / (1.f + expf(-z));
    }
}

// ---------------- launch ----------------
extern "C" void kernel_launch(void* const* d_in, const int* in_sizes, int n_in,
                              void* d_out, int out_size) {
    const float* image   = (const float*)d_in[0];
    const float* conv1_w = (const float*)d_in[1];
    const float* bn1_g   = (const float*)d_in[3];
    const float* bn1_b   = (const float*)d_in[4];
    const float* conv2_w = (const float*)d_in[5];
    const float* bn2_g   = (const float*)d_in[7];
    const float* bn2_b   = (const float*)d_in[8];
    const float* fc1_w   = (const float*)d_in[9];
    const float* bn3_g   = (const float*)d_in[11];
    const float* bn3_b   = (const float*)d_in[12];
    const float* fc2_w   = (const float*)d_in[13];
    const float* fc2_b   = (const float*)d_in[14];
    float* out = (float*)d_out;

    static bool attr_done = false;
    if (!attr_done) {
        cudaFuncSetAttribute(conv2_kernel,
                             cudaFuncAttributeMaxDynamicSharedMemorySize,
                             CONV2_SMEM_BYTES);
        attr_done = true;
    }

    layout_kernel<<<dim3(46, 64), 256>>>(image, conv2_w, conv1_w);  // idx 0
    conv1_kernel<<<dim3(13, 64), 128>>>();                          // idx 1
    bnapply1_kernel<<<5408, 256>>>(bn1_g, bn1_b);                   // idx 2
    conv2_kernel<<<dim3(2, 64), 576, CONV2_SMEM_BYTES>>>();         // idx 3 (profiled)
    fc1_kernel<<<dim3(2, 144), 256>>>(fc1_w, bn2_g, bn2_b);         // idx 4
    final_kernel<<<64, 256>>>(bn3_g, bn3_b, fc2_w, fc2_b, out);     // idx 5
}